// round 9
// baseline (speedup 1.0000x reference)
#include <cuda_runtime.h>
#include <cuda_bf16.h>
#include <math.h>

// Problem constants
#define BB   32
#define HH   14
#define WW   14
#define CC   32
#define KK   64
#define KS   5
#define OH   10
#define OW   10
#define PP   100      // OH*OW
#define NPOS 196      // H*W
#define MM   800      // KS*KS*C
#define IMG  6272     // NPOS*CC floats per batch
#define SIGB 1229312  // NPOS*NPOS*CC floats per batch of Sigma_in
#define SIGR 6304     // NPOS*CC + CC (diag row stride in floats)
#define PSTR 36       // padded smem stride per position (floats)

// Scratch (device globals)
__device__ float4 g_w4[25 * 16 * KK];      // [ij][c2][k] = {w_ev, w_od, w2_ev, w2_od}
__device__ float  g_dv[BB * PP * KK];      // diag_vals
__device__ float  g_G [BB * PP * PP];      // Gram matrices
__device__ float  g_S [BB * NPOS * NPOS];  // position-Gram S = X X^T (4.9 MB)

// ---------------- f32x2 packed helpers ----------------
typedef unsigned long long ull;

__device__ __forceinline__ ull f2fma(ull a, ull b, ull c) {
    ull d;
    asm("fma.rn.f32x2 %0, %1, %2, %3;" : "=l"(d) : "l"(a), "l"(b), "l"(c));
    return d;
}
__device__ __forceinline__ float f2sum(ull v) {
    float lo, hi;
    asm("mov.b64 {%0, %1}, %2;" : "=f"(lo), "=f"(hi) : "l"(v));
    return lo + hi;
}

// ---------------- Kernel 0: weight pack (tiny, wide) ----------------
// g_w4[ij*1024 + c2*64 + k] = {w[ij*32+2c2][k], w[ij*32+2c2+1][k], sq, sq}
__global__ __launch_bounds__(256) void k_prep_w(const float* __restrict__ w_mu) {
    int idx = blockIdx.x * 256 + threadIdx.x;        // 25600 total
    if (idx >= 25600) return;
    int ij = idx >> 10;
    int r  = idx & 1023;
    int c2 = r >> 6;
    int k  = r & 63;
    float w0 = w_mu[(ij * 32 + 2 * c2) * KK + k];
    float w1 = w_mu[(ij * 32 + 2 * c2 + 1) * KK + k];
    g_w4[idx] = make_float4(w0, w1, w0 * w0, w1 * w1);
}

// ---------------- Kernel A: mu_out + diag_vals ----------------
// grid (5 pt, 4 kq, 32 b) = 640 blocks, 64 threads (2 warps).
// kk = tid&15 (one k of this quarter), pg = tid>>4 owns p_local = pg*5 + {0..4}.
// Per-tap weight stage (16 c2 x 16 k float4 = 4KB) via register prefetch + STS.
__global__ __launch_bounds__(64) void k_mu_diag(const float* __restrict__ mu_in,
                                                const float* __restrict__ Sg,
                                                const float* __restrict__ w_sigma,
                                                float* __restrict__ out_mu) {
    __shared__ __align__(16) float4 s_w4[256];       // [c2(16)][kk(16)]
    __shared__ __align__(16) float  s_mu[84 * PSTR]; // 6 rows x 14 pos, padded
    __shared__ __align__(16) float  s_ds[84 * PSTR];
    __shared__ float s_S[84];
    __shared__ float s_tr[20];

    int tid = threadIdx.x;
    int pt  = blockIdx.x;            // 0..4 -> output rows 2pt, 2pt+1
    int kq  = blockIdx.y;            // 0..3 -> k quarter
    int b   = blockIdx.z;
    int kk  = tid & 15;
    int pg  = tid >> 4;              // 0..3

    // --- prefetch weight stage 0 (tap 0, this k-quarter) ---
    float4 pf[4];
    #pragma unroll
    for (int it = 0; it < 4; it++) {
        int f = tid + it * 64;                       // 0..255 = c2*16 + kkl
        pf[it] = __ldg(g_w4 + (f >> 4) * 64 + kq * 16 + (f & 15));
    }

    // --- fused load: mu tile (6 image rows) + Sigma-diag gather + channel sums ---
    {
        const float4* msrc = reinterpret_cast<const float4*>(mu_in + b * IMG + pt * 28 * 32);
        const float*  sb   = Sg + b * SIGB;
        int c4 = tid & 7;
        for (int t = tid; t < 672; t += 64) {
            int pos_l = t >> 3;                      // 0..83
            float4 mv = msrc[t];
            *reinterpret_cast<float4*>(s_mu + pos_l * PSTR + c4 * 4) = mv;
            int pos = pt * 28 + pos_l;
            float4 sg = *reinterpret_cast<const float4*>(sb + pos * SIGR + c4 * 4);
            *reinterpret_cast<float4*>(s_ds + pos_l * PSTR + c4 * 4) = sg;
            float part = sg.x + sg.y + sg.z + sg.w;
            part += __shfl_down_sync(0xffffffffu, part, 4, 8);
            part += __shfl_down_sync(0xffffffffu, part, 2, 8);
            part += __shfl_down_sync(0xffffffffu, part, 1, 8);
            if (c4 == 0) s_S[pos_l] = part;
        }
    }
    __syncthreads();

    // --- trace per patch (20 p's) ---
    if (tid < 20) {
        int pr = tid / 10, pc = tid % 10;
        float s = 0.f;
        #pragma unroll
        for (int i = 0; i < KS; i++)
            #pragma unroll
            for (int j = 0; j < KS; j++)
                s += s_S[(pr + i) * 14 + pc + j];
        s_tr[tid] = s;
    }

    // p bases for this thread's 5 patches
    int pbase[5];
    #pragma unroll
    for (int jp = 0; jp < 5; jp++) {
        int pl = pg * 5 + jp;                        // 0..19
        int pr = pl / 10, pc = pl % 10;
        pbase[jp] = (pr * 14 + pc) * PSTR;
    }

    ull accM[5], accV[5];
    #pragma unroll
    for (int jp = 0; jp < 5; jp++) { accM[jp] = 0ull; accV[jp] = 0ull; }

    // --- main loop over 25 kernel taps ---
    #pragma unroll 1
    for (int ij = 0; ij < 25; ij++) {
        __syncthreads();                 // previous tap's reads of s_w4 complete
        #pragma unroll
        for (int it = 0; it < 4; it++)
            s_w4[tid + it * 64] = pf[it];            // conflict-free STS.128
        if (ij + 1 < 25) {
            const float4* ws = g_w4 + (ij + 1) * 1024 + kq * 16;
            #pragma unroll
            for (int it = 0; it < 4; it++) {
                int f = tid + it * 64;
                pf[it] = __ldg(ws + (f >> 4) * 64 + (f & 15));
            }
        }
        __syncthreads();                 // stage ij visible

        int i = ij / 5, j = ij % 5;
        int sh = (i * 14 + j) * PSTR;

        #pragma unroll
        for (int c4 = 0; c4 < 8; c4++) {
            // {w pair, w^2 pair} for channel pairs 2c4 and 2c4+1, this thread's k
            ulonglong2 wA = *reinterpret_cast<const ulonglong2*>(s_w4 + (2 * c4) * 16 + kk);
            ulonglong2 wB = *reinterpret_cast<const ulonglong2*>(s_w4 + (2 * c4 + 1) * 16 + kk);
            #pragma unroll
            for (int jp = 0; jp < 5; jp++) {
                int off = pbase[jp] + sh + c4 * 4;
                ulonglong2 a = *reinterpret_cast<const ulonglong2*>(s_mu + off);
                ulonglong2 d = *reinterpret_cast<const ulonglong2*>(s_ds + off);
                accM[jp] = f2fma(a.x, wA.x, accM[jp]);
                accM[jp] = f2fma(a.y, wB.x, accM[jp]);
                accV[jp] = f2fma(d.x, wA.y, accV[jp]);
                accV[jp] = f2fma(d.y, wB.y, accV[jp]);
            }
        }
    }

    int kg = kq * 16 + kk;
    float spk = log1pf(expf(w_sigma[kg]));
    #pragma unroll
    for (int jp = 0; jp < 5; jp++) {
        int pl = pg * 5 + jp;
        int p  = pt * 20 + pl;
        int base = (b * PP + p) * KK + kg;
        out_mu[base] = f2sum(accM[jp]);
        g_dv[base]   = f2sum(accV[jp]) + spk * s_tr[pl];
    }
}

// ---------------- Kernel B1: S = X X^T (wide) ----------------
__global__ __launch_bounds__(256) void k_gram_s(const float* __restrict__ mu_in) {
    __shared__ __align__(16) float2 s_yc[16 * 200];   // [c2][pos], padded

    int tid = threadIdx.x;
    int b   = blockIdx.y;
    int x0  = blockIdx.x * 28;
    const float* mb = mu_in + b * IMG;

    for (int t = tid; t < 16 * NPOS; t += 256) {
        int c2 = t & 15, pos = t >> 4;
        s_yc[c2 * 200 + pos] = *reinterpret_cast<const float2*>(mb + pos * 32 + c2 * 2);
    }
    __syncthreads();

    int lane = tid & 31, wrp = tid >> 5;
    float* Sb = g_S + b * (NPOS * NPOS);

    #pragma unroll 1
    for (int r = 0; r < 4; r++) {
        int xl = wrp + 8 * r;
        if (xl >= 28) break;
        int x = x0 + xl;

        ull xc[16];
        #pragma unroll
        for (int c2 = 0; c2 < 16; c2++)
            xc[c2] = *reinterpret_cast<const ull*>(s_yc + c2 * 200 + x);   // broadcast

        #pragma unroll 1
        for (int m = 0; m < 4; m++) {
            int pr = lane + 32 * m;
            if (pr >= 98) break;
            int y0 = 2 * pr;
            ull acc0 = 0ull, acc1 = 0ull;
            #pragma unroll
            for (int c2 = 0; c2 < 16; c2++) {
                ulonglong2 v = *reinterpret_cast<const ulonglong2*>(s_yc + c2 * 200 + y0);
                acc0 = f2fma(xc[c2], v.x, acc0);
                acc1 = f2fma(xc[c2], v.y, acc1);
            }
            float2 rr;
            rr.x = f2sum(acc0);
            rr.y = f2sum(acc1);
            *reinterpret_cast<float2*>(Sb + x * NPOS + y0) = rr;
        }
    }
}

// ---------------- Kernel B2: G[p,q] = 25-shift diagonal sum of S ----------------
__global__ __launch_bounds__(256) void k_gram_g() {
    int tid = threadIdx.x;
    int pt  = blockIdx.x;
    int b   = blockIdx.y;
    const float* Sb = g_S + b * (NPOS * NPOS);
    float* Gb = g_G + b * (PP * PP);

    #pragma unroll 1
    for (int idx = tid; idx < 25 * PP; idx += 256) {
        int p_l = idx / PP, q = idx - p_l * PP;
        int p  = pt * 25 + p_l;
        int pr = p / 10, pc = p - pr * 10;
        int qr = q / 10, qc = q - qr * 10;
        const float* s = Sb + (pr * 14 + pc) * NPOS + (qr * 14 + qc);
        float acc = 0.f;
        #pragma unroll
        for (int i = 0; i < KS; i++)
            #pragma unroll
            for (int j = 0; j < KS; j++)
                acc += __ldg(s + (i * 14 + j) * (NPOS + 1));
        Gb[p * PP + q] = acc;
    }
}

// ---------------- Kernel C: expand Sigma_out (pure bandwidth) ----------------
__global__ __launch_bounds__(256) void k_expand(const float* __restrict__ w_sigma,
                                                float* __restrict__ out) {
    __shared__ float  s_g[PP];
    __shared__ float4 s_sp[16];
    __shared__ float4 s_dv[16];

    int tid = threadIdx.x;
    int p = blockIdx.x, b = blockIdx.y;
    int bp = b * PP + p;

    if (tid < PP) s_g[tid] = g_G[b * (PP * PP) + p * PP + tid];
    if (tid >= 128 && tid < 144) {
        int k4 = (tid - 128) * 4;
        float4 sp;
        sp.x = log1pf(expf(w_sigma[k4]));
        sp.y = log1pf(expf(w_sigma[k4 + 1]));
        sp.z = log1pf(expf(w_sigma[k4 + 2]));
        sp.w = log1pf(expf(w_sigma[k4 + 3]));
        s_sp[tid - 128] = sp;
    }
    if (tid >= 160 && tid < 176)
        s_dv[tid - 160] = *reinterpret_cast<const float4*>(g_dv + bp * KK + (tid - 160) * 4);
    __syncthreads();

    float* orow = out + BB * PP * KK + bp * (PP * KK);

    #pragma unroll
    for (int it = 0; it < 7; it++) {
        int v = tid + it * 256;
        if (v < PP * 16) {
            int q = v >> 4, kc = v & 15, k4 = kc * 4;
            float g = s_g[q];
            float4 sp = s_sp[kc];
            float4 r;
            r.x = sp.x * g; r.y = sp.y * g; r.z = sp.z * g; r.w = sp.w * g;
            if (q == p) {
                float4 dv = s_dv[kc];
                r.x += dv.x; r.y += dv.y; r.z += dv.z; r.w += dv.w;
            }
            r.x = isfinite(r.x) ? r.x : 0.f;
            r.y = isfinite(r.y) ? r.y : 0.f;
            r.z = isfinite(r.z) ? r.z : 0.f;
            r.w = isfinite(r.w) ? r.w : 0.f;
            if (q == k4)     r.x = fabsf(r.x);
            if (q == k4 + 1) r.y = fabsf(r.y);
            if (q == k4 + 2) r.z = fabsf(r.z);
            if (q == k4 + 3) r.w = fabsf(r.w);
            *reinterpret_cast<float4*>(orow + 4 * v) = r;
        }
    }
}

// ---------------- launch ----------------
extern "C" void kernel_launch(void* const* d_in, const int* in_sizes, int n_in,
                              void* d_out, int out_size) {
    const float* mu_in    = (const float*)d_in[0];
    const float* Sigma_in = (const float*)d_in[1];
    const float* w_mu     = (const float*)d_in[2];
    const float* w_sigma  = (const float*)d_in[3];
    float* out = (float*)d_out;

    static cudaStream_t s2 = nullptr;
    static cudaEvent_t  eFork = nullptr, eJoin = nullptr;
    if (s2 == nullptr) {
        cudaStreamCreateWithFlags(&s2, cudaStreamNonBlocking);
        cudaEventCreateWithFlags(&eFork, cudaEventDisableTiming);
        cudaEventCreateWithFlags(&eJoin, cudaEventDisableTiming);
    }

    // side stream: Gram chain (depends only on mu_in)
    cudaEventRecord(eFork, 0);
    cudaStreamWaitEvent(s2, eFork, 0);
    k_gram_s<<<dim3(7, BB), 256, 0, s2>>>(mu_in);
    k_gram_g<<<dim3(4, BB), 256, 0, s2>>>();
    cudaEventRecord(eJoin, s2);

    // main stream: mu path
    k_prep_w<<<100, 256>>>(w_mu);
    k_mu_diag<<<dim3(5, 4, BB), 64>>>(mu_in, Sigma_in, w_sigma, out);

    cudaStreamWaitEvent(0, eJoin, 0);
    k_expand<<<dim3(PP, BB), 256>>>(w_sigma, out);
}